// round 4
// baseline (speedup 1.0000x reference)
#include <cuda_runtime.h>
#include <math.h>

#define HX_B 16
#define HX_C 256
#define HX_H 128
#define HX_W 128
#define HX_HW (HX_H * HX_W)      // 16384
#define HX_HW4 (HX_HW / 4)       // 4096

#define CH_B 4                   // batches per chunk (64 MiB of x -> fits L2)
#define NCHUNK (HX_B / CH_B)     // 4 chunks

#define RED_SLICES 16            // C split 16 ways
#define RED_CPT (HX_C / RED_SLICES)  // 16 channels per thread
#define RED_PIX 16               // float4 pixels per block (block = 16x16 = 256)

// scratch (device globals: allocation-free per harness rules)
__device__ float g_avg[HX_B * HX_HW];   // 1 MiB
__device__ float g_max[HX_B * HX_HW];   // 1 MiB
__device__ float g_sig[HX_B * HX_HW];   // 1 MiB

// ---------------------------------------------------------------------------
// Kernel 1 (per chunk): mean & max over C=256 for CH_B batches.
// block = 256 threads = 16 slices x 16 pixels; each thread reduces 16 channels.
// grid per chunk = CH_B*HW4/16 = 1024 blocks -> occ ~85%.
// Warp = 2 slices x 16 pix -> two contiguous 256B segments: fully coalesced.
// ---------------------------------------------------------------------------
__global__ void __launch_bounds__(256) reduce_kernel(const float4* __restrict__ x4,
                                                     int b0) {
    __shared__ float4 s_sum[RED_SLICES * RED_PIX];
    __shared__ float4 s_max[RED_SLICES * RED_PIX];

    int tid   = threadIdx.x;
    int pix   = tid & (RED_PIX - 1);        // 0..15
    int slice = tid >> 4;                   // 0..15
    int lpix  = blockIdx.x * RED_PIX + pix; // 0..CH_B*HW4-1
    int b     = b0 + (lpix >> 12);          // /HX_HW4 (4096)
    int hw4   = lpix & (HX_HW4 - 1);

    const float4* p = x4 + (size_t)b * HX_C * HX_HW4
                         + (size_t)(slice * RED_CPT) * HX_HW4 + hw4;

    float sx = 0.f, sy = 0.f, sz = 0.f, sw = 0.f;
    float mx = -INFINITY, my = -INFINITY, mz = -INFINITY, mw = -INFINITY;
    #pragma unroll
    for (int c = 0; c < RED_CPT; c++) {
        float4 v = p[(size_t)c * HX_HW4];
        sx += v.x; sy += v.y; sz += v.z; sw += v.w;
        mx = fmaxf(mx, v.x); my = fmaxf(my, v.y);
        mz = fmaxf(mz, v.z); mw = fmaxf(mw, v.w);
    }
    s_sum[tid] = make_float4(sx, sy, sz, sw);
    s_max[tid] = make_float4(mx, my, mz, mw);
    __syncthreads();

    if (slice == 0) {
        float4 a = s_sum[pix];
        float4 m = s_max[pix];
        #pragma unroll
        for (int k = 1; k < RED_SLICES; k++) {
            float4 a2 = s_sum[k * RED_PIX + pix];
            float4 m2 = s_max[k * RED_PIX + pix];
            a.x += a2.x; a.y += a2.y; a.z += a2.z; a.w += a2.w;
            m.x = fmaxf(m.x, m2.x); m.y = fmaxf(m.y, m2.y);
            m.z = fmaxf(m.z, m2.z); m.w = fmaxf(m.w, m2.w);
        }
        const float inv = 1.0f / HX_C;
        a.x *= inv; a.y *= inv; a.z *= inv; a.w *= inv;
        int gpix = b * HX_HW4 + hw4;
        reinterpret_cast<float4*>(g_avg)[gpix] = a;
        reinterpret_cast<float4*>(g_max)[gpix] = m;
    }
}

// ---------------------------------------------------------------------------
// Kernel 2 (per chunk, tiny): cross stencil with zero padding + sigmoid.
// ---------------------------------------------------------------------------
__global__ void __launch_bounds__(256) stencil_kernel(const float* __restrict__ wts,
                                                      int b0) {
    int li = blockIdx.x * blockDim.x + threadIdx.x;   // over CH_B*HW
    int b  = b0 + (li >> 14);                         // /HX_HW (16384)
    int hw = li & (HX_HW - 1);
    int h  = hw >> 7;          // /128
    int w  = hw & 127;

    float acc = 0.f;
    #pragma unroll
    for (int m = 0; m < 2; m++) {
        const float* y = (m == 0 ? g_avg : g_max) + b * HX_HW;
        float p0 = wts[b * 8 + m * 4 + 0];
        float p1 = wts[b * 8 + m * 4 + 1];
        float p2 = wts[b * 8 + m * 4 + 2];
        float p3 = wts[b * 8 + m * 4 + 3];
        float pc = -(p0 + p1 + p2 + p3);
        float top = (h > 0)            ? y[hw - HX_W] : 0.f;
        float bot = (h < HX_H - 1)     ? y[hw + HX_W] : 0.f;
        float lft = (w > 0)            ? y[hw - 1]    : 0.f;
        float rgt = (w < HX_W - 1)     ? y[hw + 1]    : 0.f;
        acc += p0 * top + p1 * bot + p2 * lft + p3 * rgt + pc * y[hw];
    }
    g_sig[b * HX_HW + hw] = 1.0f / (1.0f + __expf(-acc));
}

// ---------------------------------------------------------------------------
// Kernel 3 (per chunk): out = x * (1 + sig). x read should hit L2 (just
// streamed by reduce of the same chunk). __ldcs/__stcs: evict-first, so this
// chunk's dead lines don't push out the next chunk's working set.
// ---------------------------------------------------------------------------
__global__ void __launch_bounds__(256) apply_kernel(const float4* __restrict__ x4,
                                                    float4* __restrict__ o4,
                                                    int b0) {
    int li = blockIdx.x * blockDim.x + threadIdx.x;   // over CH_B*C*HW4
    size_t gi = (size_t)b0 * HX_C * HX_HW4 + li;
    int b   = b0 + li / (HX_C * HX_HW4);
    int hw4 = li & (HX_HW4 - 1);
    float4 s = reinterpret_cast<const float4*>(g_sig)[b * HX_HW4 + hw4];
    float4 v = __ldcs(x4 + gi);
    float4 o;
    o.x = v.x * (1.0f + s.x);
    o.y = v.y * (1.0f + s.y);
    o.z = v.z * (1.0f + s.z);
    o.w = v.w * (1.0f + s.w);
    __stcs(o4 + gi, o);
}

extern "C" void kernel_launch(void* const* d_in, const int* in_sizes, int n_in,
                              void* d_out, int out_size) {
    const float4* x4  = (const float4*)d_in[0];
    const float*  wts = (const float*)d_in[1];
    float4*       o4  = (float4*)d_out;

    for (int ch = 0; ch < NCHUNK; ch++) {
        int b0 = ch * CH_B;
        // reduce: CH_B*HW4*16 threads / 256 = 1024 blocks
        reduce_kernel<<<CH_B * HX_HW4 / RED_PIX, 256>>>(x4, b0);
        // stencil: CH_B*HW / 256 = 256 blocks
        stencil_kernel<<<CH_B * HX_HW / 256, 256>>>(wts, b0);
        // apply: CH_B*C*HW4 / 256 = 16384 blocks
        apply_kernel<<<CH_B * HX_C * HX_HW4 / 256, 256>>>(x4, o4, b0);
    }
}